// round 1
// baseline (speedup 1.0000x reference)
#include <cuda_runtime.h>
#include <math.h>

#define NB 64
#define NQ 128
#define ND 512
#define NP 129
#define INF_ 1e9f
#define EPS_ 1e-8f

// scratch (device globals; no allocation allowed)
__device__ float g_rn[NB * NQ * ND];
__device__ float g_en[NB * NQ * ND];
__device__ float g_cost[NB * NQ * NQ];

// ---------------------------------------------------------------------------
// Kernel 1: row-wise normalize  (x + 1e-8) / max(||x+1e-8||, 1e-8)
// One warp per row of 512. 2*B*Q = 16384 rows.
// ---------------------------------------------------------------------------
__global__ void normalize_kernel(const float* __restrict__ r,
                                 const float* __restrict__ e) {
    int gw = (blockIdx.x * blockDim.x + threadIdx.x) >> 5;
    int lane = threadIdx.x & 31;
    if (gw >= 2 * NB * NQ) return;
    const float* src;
    float* dst;
    if (gw < NB * NQ) { src = r + (size_t)gw * ND;            dst = g_rn + (size_t)gw * ND; }
    else              { src = e + (size_t)(gw - NB*NQ) * ND;  dst = g_en + (size_t)(gw - NB*NQ) * ND; }

    float vals[16];
    float ss = 0.f;
#pragma unroll
    for (int k = 0; k < 16; k++) {
        float x = src[lane + 32 * k] + EPS_;
        vals[k] = x;
        ss += x * x;
    }
#pragma unroll
    for (int o = 16; o > 0; o >>= 1)
        ss += __shfl_xor_sync(0xffffffffu, ss, o);
    float n = sqrtf(ss);
    float s = 1.f / fmaxf(n, EPS_);
#pragma unroll
    for (int k = 0; k < 16; k++)
        dst[lane + 32 * k] = vals[k] * s;
}

// ---------------------------------------------------------------------------
// Kernel 2: batched cost GEMM  cost[b][i][j] = -sum_d rn[b][i][d]*en[b][j][d]
// Grid: (tj=2, ti=2, b=64). Block 16x16, 64x64 tile, 4x4 per thread, k-chunk 32.
// ---------------------------------------------------------------------------
__global__ void cost_kernel() {
    __shared__ float sr[64][33];
    __shared__ float se[64][33];
    int b  = blockIdx.z;
    int ti = blockIdx.y;
    int tj = blockIdx.x;
    const float* rb = g_rn + (size_t)b * NQ * ND + (size_t)ti * 64 * ND;
    const float* eb = g_en + (size_t)b * NQ * ND + (size_t)tj * 64 * ND;
    int tx = threadIdx.x, ty = threadIdx.y;
    int tid = ty * 16 + tx;

    float acc[4][4];
#pragma unroll
    for (int u = 0; u < 4; u++)
#pragma unroll
        for (int v = 0; v < 4; v++) acc[u][v] = 0.f;

    for (int k0 = 0; k0 < ND; k0 += 32) {
        for (int t = tid; t < 64 * 32; t += 256) {
            int row = t >> 5, kk = t & 31;
            sr[row][kk] = rb[(size_t)row * ND + k0 + kk];
            se[row][kk] = eb[(size_t)row * ND + k0 + kk];
        }
        __syncthreads();
#pragma unroll 8
        for (int kk = 0; kk < 32; kk++) {
            float a[4], bb[4];
#pragma unroll
            for (int u = 0; u < 4; u++) a[u]  = sr[ty * 4 + u][kk];
#pragma unroll
            for (int u = 0; u < 4; u++) bb[u] = se[tx * 4 + u][kk];
#pragma unroll
            for (int u = 0; u < 4; u++)
#pragma unroll
                for (int v = 0; v < 4; v++)
                    acc[u][v] += a[u] * bb[v];
        }
        __syncthreads();
    }

    float* cb = g_cost + (size_t)b * NQ * NQ;
#pragma unroll
    for (int u = 0; u < 4; u++) {
        int i = ti * 64 + ty * 4 + u;
#pragma unroll
        for (int v = 0; v < 4; v++) {
            int j = tj * 64 + tx * 4 + v;
            cb[i * NQ + j] = -acc[u][v];
        }
    }
}

// ---------------------------------------------------------------------------
// Kernel 3: zero the loss accumulator
// ---------------------------------------------------------------------------
__global__ void zero_kernel(float* out) { out[0] = 0.f; }

// ---------------------------------------------------------------------------
// Kernel 4: Jonker-Volgenant LSA, one CTA per batch, warp 0 runs the solve.
// Cost tile staged in dynamic SMEM (64KB). Lane l owns columns j = l + 32k,
// k in [0,5). Duals v and minv live in registers; u, p, way in static SMEM.
// Ends by writing col (as float) and atomically accumulating the loss.
// ---------------------------------------------------------------------------
__global__ void lsa_kernel(float* __restrict__ out) {
    extern __shared__ float costS[];      // NQ*NQ floats
    __shared__ float uS[NP];
    __shared__ int   pS[NP];
    __shared__ int   wayS[NP];

    int b   = blockIdx.x;
    int tid = threadIdx.x;

    const float* cb = g_cost + (size_t)b * NQ * NQ;
    for (int t = tid; t < NQ * NQ; t += blockDim.x) costS[t] = cb[t];
    if (tid < NP) { uS[tid] = 0.f; pS[tid] = 0; wayS[tid] = 0; }
    __syncthreads();
    if (tid >= 32) return;   // warp 0 only from here; only __syncwarp below

    const unsigned FULL = 0xffffffffu;
    int lane = tid;

    float v_r[5];
#pragma unroll
    for (int k = 0; k < 5; k++) v_r[k] = 0.f;

    for (int i = 1; i <= NQ; i++) {
        if (lane == 0) pS[0] = i;
        unsigned usedb = 0u;
        float minv_r[5];
#pragma unroll
        for (int k = 0; k < 5; k++) minv_r[k] = INF_;
        __syncwarp();

        int j0 = 0;
        while (true) {
            // mark used[j0]
            if ((j0 & 31) == lane) usedb |= 1u << (j0 >> 5);
            int   i0  = pS[j0];
            float ui0 = uS[i0];

            // reduced costs of row i0, update minv/way
#pragma unroll
            for (int k = 0; k < 5; k++) {
                int j = lane + 32 * k;
                if (j <= NQ && !((usedb >> k) & 1u)) {
                    float c   = (j == 0) ? 0.f : costS[(i0 - 1) * NQ + (j - 1)];
                    float cur = c - ui0 - v_r[k];
                    if (cur < minv_r[k]) { minv_r[k] = cur; wayS[j] = j0; }
                }
            }

            // argmin over unused columns, tie-break = lowest j (match jnp.argmin)
            float bv = INF_ * 4.f;
            int   bj = 1 << 30;
#pragma unroll
            for (int k = 0; k < 5; k++) {
                int j = lane + 32 * k;
                if (j <= NQ && !((usedb >> k) & 1u) && minv_r[k] < bv) {
                    bv = minv_r[k]; bj = j;
                }
            }
#pragma unroll
            for (int o = 16; o > 0; o >>= 1) {
                float ov = __shfl_down_sync(FULL, bv, o);
                int   oj = __shfl_down_sync(FULL, bj, o);
                if (ov < bv || (ov == bv && oj < bj)) { bv = ov; bj = oj; }
            }
            bv = __shfl_sync(FULL, bv, 0);
            bj = __shfl_sync(FULL, bj, 0);
            float delta = bv;

            // dual updates
#pragma unroll
            for (int k = 0; k < 5; k++) {
                int j = lane + 32 * k;
                if (j <= NQ) {
                    if ((usedb >> k) & 1u) {
                        uS[pS[j]] += delta;   // distinct rows -> no conflict
                        v_r[k]    -= delta;
                    } else {
                        minv_r[k] -= delta;
                    }
                }
            }
            __syncwarp();

            j0 = bj;
            if (pS[j0] == 0) break;   // free column found
        }

        // augment along 'way'
        if (lane == 0) {
            int j = j0;
            while (j != 0) {
                int j1 = wayS[j];
                pS[j]  = pS[j1];
                j = j1;
            }
        }
        __syncwarp();
    }

    // Epilogue: col[row] = j-1 where p[j] = row+1 ; sim = -cost[row][j-1]
    float simsum = 0.f;
#pragma unroll
    for (int k = 0; k < 5; k++) {
        int j = lane + 32 * k;
        if (j >= 1 && j <= NQ) {
            int row = pS[j] - 1;
            simsum += -costS[row * NQ + (j - 1)];
            out[1 + b * NQ + row] = (float)(j - 1);
        }
    }
#pragma unroll
    for (int o = 16; o > 0; o >>= 1)
        simsum += __shfl_xor_sync(FULL, simsum, o);
    if (lane == 0)
        atomicAdd(out, (1.f - simsum * (1.f / NQ)) * (1.f / NB));
}

// ---------------------------------------------------------------------------
extern "C" void kernel_launch(void* const* d_in, const int* in_sizes, int n_in,
                              void* d_out, int out_size) {
    const float* r = (const float*)d_in[0];
    const float* e = (const float*)d_in[1];
    float* out = (float*)d_out;

    cudaFuncSetAttribute(lsa_kernel,
                         cudaFuncAttributeMaxDynamicSharedMemorySize,
                         NQ * NQ * (int)sizeof(float));

    // 16384 warps for normalize, 8 warps/block
    normalize_kernel<<<(2 * NB * NQ) / 8, 256>>>(r, e);

    dim3 gg(2, 2, NB);
    cost_kernel<<<gg, dim3(16, 16)>>>();

    zero_kernel<<<1, 1>>>(out);

    lsa_kernel<<<NB, 256, NQ * NQ * (int)sizeof(float)>>>(out);
}